// round 1
// baseline (speedup 1.0000x reference)
#include <cuda_runtime.h>
#include <math.h>

// ---------------------------------------------------------------------------
// Problem constants
// ---------------------------------------------------------------------------
#define NBATCH 2
#define OD 8
#define OH 28
#define OW 28
#define S_OUT 6272              // 8*28*28
#define NS 12544                // NBATCH * S_OUT

// x: [2,64,16,56,56]; out1/out2: stored channel-major [C][N*S_OUT]
// cols buffer: max K = 128*27 = 3456 rows -> 3456*12544 floats
__device__ float g_cols[43352064];
__device__ float g_off1[8128512];    // 648  * NS
__device__ float g_off2[16257024];   // 1296 * NS
__device__ float g_out1[1605632];    // 128  * NS
__device__ float g_out2[1605632];    // 128  * NS
__device__ float g_res[802816];      // 64   * NS
__device__ float g_mean[128];
__device__ float g_istd[128];

// ---------------------------------------------------------------------------
// maxpool3d k3 s2 p1 on x -> residual [64][NS]
// ---------------------------------------------------------------------------
__global__ void maxpool_kernel(const float* __restrict__ x, float* __restrict__ res) {
    int i = blockIdx.x * blockDim.x + threadIdx.x;
    if (i >= 64 * NS) return;
    int ns = i % NS;
    int c  = i / NS;
    int n  = ns / S_OUT;
    int s  = ns % S_OUT;
    int od = s / (OH * OW);
    int oh = (s / OW) % OH;
    int ow = s % OW;
    const float* xp = x + ((size_t)(n * 64 + c)) * 16 * 56 * 56;
    int d0 = od * 2 - 1, h0 = oh * 2 - 1, w0 = ow * 2 - 1;
    int dlo = d0 < 0 ? 0 : d0, dhi = d0 + 2 > 15 ? 15 : d0 + 2;
    int hlo = h0 < 0 ? 0 : h0, hhi = h0 + 2 > 55 ? 55 : h0 + 2;
    int wlo = w0 < 0 ? 0 : w0, whi = w0 + 2 > 55 ? 55 : w0 + 2;
    float m = -INFINITY;
    for (int dd = dlo; dd <= dhi; dd++)
        for (int hh = hlo; hh <= hhi; hh++)
            for (int ww = wlo; ww <= whi; ww++)
                m = fmaxf(m, xp[(dd * 56 + hh) * 56 + ww]);
    res[(size_t)c * NS + ns] = m;
}

// ---------------------------------------------------------------------------
// Regular im2col (3x3x3, pad 1). Input either NCDHW (ncdhw=1) or channel-major
// [C][NBATCH*Sin] (ncdhw=0). Output cols[(c*27+tap)][ns].
// ---------------------------------------------------------------------------
__global__ void im2col_kernel(const float* __restrict__ in, float* __restrict__ cols,
                              int C, int Din, int Hin, int Win, int stride, int ncdhw) {
    long long i = (long long)blockIdx.x * blockDim.x + threadIdx.x;
    long long total = (long long)C * 27 * NS;
    if (i >= total) return;
    int ns  = (int)(i % NS);
    int ct  = (int)(i / NS);
    int tap = ct % 27;
    int c   = ct / 27;
    int n   = ns / S_OUT;
    int s   = ns % S_OUT;
    int od = s / (OH * OW);
    int oh = (s / OW) % OH;
    int ow = s % OW;
    int kd = tap / 9, kh = (tap / 3) % 3, kw = tap % 3;
    int id = od * stride - 1 + kd;
    int ih = oh * stride - 1 + kh;
    int iw = ow * stride - 1 + kw;
    float v = 0.f;
    if (id >= 0 && id < Din && ih >= 0 && ih < Hin && iw >= 0 && iw < Win) {
        size_t Sin = (size_t)Din * Hin * Win;
        size_t base = ncdhw ? ((size_t)(n * C + c)) * Sin
                            : ((size_t)c * NBATCH + n) * Sin;
        v = in[base + ((size_t)id * Hin + ih) * Win + iw];
    }
    cols[(size_t)ct * NS + ns] = v;
}

// ---------------------------------------------------------------------------
// Deformable im2col. One thread handles one (group, tap, ns): computes the
// sampling position once, reuses the 8 corner indices/weights for all
// cpg=8 channels in the group. Offsets: off[((g*3+coord)*27+tap)][ns].
// ---------------------------------------------------------------------------
__global__ void deform_im2col_kernel(const float* __restrict__ in,
                                     const float* __restrict__ off,
                                     float* __restrict__ cols,
                                     int C, int G, int Din, int Hin, int Win,
                                     int stride, int ncdhw) {
    long long i = (long long)blockIdx.x * blockDim.x + threadIdx.x;
    long long total = (long long)G * 27 * NS;
    if (i >= total) return;
    int ns  = (int)(i % NS);
    int gt  = (int)(i / NS);
    int tap = gt % 27;
    int g   = gt / 27;
    int n   = ns / S_OUT;
    int s   = ns % S_OUT;
    int od = s / (OH * OW);
    int oh = (s / OW) % OH;
    int ow = s % OW;
    int kd = tap / 9, kh = (tap / 3) % 3, kw = tap % 3;

    size_t ob = ((size_t)(g * 3) * 27 + tap) * NS + ns;
    float pd = off[ob]                     + (float)(od * stride - 1 + kd);
    float ph = off[ob + (size_t)27 * NS]   + (float)(oh * stride - 1 + kh);
    float pw = off[ob + (size_t)54 * NS]   + (float)(ow * stride - 1 + kw);

    float d0f = floorf(pd), h0f = floorf(ph), w0f = floorf(pw);
    int d0 = (int)d0f, h0 = (int)h0f, w0 = (int)w0f;
    float fd = pd - d0f, fh = ph - h0f, fw = pw - w0f;

    float wt8[8];
    int   idx8[8];
    int Sin = Din * Hin * Win;
#pragma unroll
    for (int cr = 0; cr < 8; cr++) {
        int cd = cr >> 2, ch = (cr >> 1) & 1, cw = cr & 1;
        int di = d0 + cd, hi = h0 + ch, wi = w0 + cw;
        bool valid = (di >= 0) && (di < Din) && (hi >= 0) && (hi < Hin) &&
                     (wi >= 0) && (wi < Win);
        float wt = (cd ? fd : 1.f - fd) * (ch ? fh : 1.f - fh) * (cw ? fw : 1.f - fw);
        wt8[cr] = valid ? wt : 0.f;
        int dic = di < 0 ? 0 : (di > Din - 1 ? Din - 1 : di);
        int hic = hi < 0 ? 0 : (hi > Hin - 1 ? Hin - 1 : hi);
        int wic = wi < 0 ? 0 : (wi > Win - 1 ? Win - 1 : wi);
        idx8[cr] = (dic * Hin + hic) * Win + wic;
    }
#pragma unroll
    for (int cc = 0; cc < 8; cc++) {
        int c = g * 8 + cc;
        size_t base = ncdhw ? ((size_t)(n * C + c)) * Sin
                            : ((size_t)c * NBATCH + n) * Sin;
        const float* bp = in + base;
        float acc = 0.f;
#pragma unroll
        for (int cr = 0; cr < 8; cr++) acc += wt8[cr] * bp[idx8[cr]];
        cols[((size_t)c * 27 + tap) * NS + ns] = acc;
    }
}

// ---------------------------------------------------------------------------
// Tiled SGEMM: C[M][NN] = A[M][K] * B[K][NN] (+ bias[m]). Row-major all.
// NN % BN == 0 and K % BK == 0 guaranteed by problem sizes; M guarded.
// ---------------------------------------------------------------------------
template <int BM, int BN, int BK, int TM, int TN>
__global__ void sgemm(const float* __restrict__ A, const float* __restrict__ B,
                      const float* __restrict__ bias, float* __restrict__ C,
                      int M, int NN, int K) {
    constexpr int THREADS = (BM / TM) * (BN / TN);
    __shared__ float As[BK][BM];
    __shared__ float Bs[BK][BN];
    int tid = threadIdx.x;
    int tx = tid % (BN / TN);
    int ty = tid / (BN / TN);
    int row0 = blockIdx.y * BM;
    int col0 = blockIdx.x * BN;

    float acc[TM][TN];
#pragma unroll
    for (int i = 0; i < TM; i++)
#pragma unroll
        for (int j = 0; j < TN; j++) acc[i][j] = 0.f;

    for (int k0 = 0; k0 < K; k0 += BK) {
#pragma unroll
        for (int e = tid; e < BM * BK; e += THREADS) {
            int m = e / BK, k = e % BK;
            int gm = row0 + m;
            As[k][m] = (gm < M) ? A[(size_t)gm * K + k0 + k] : 0.f;
        }
#pragma unroll
        for (int e = tid; e < BK * BN; e += THREADS) {
            int kk = e / BN, nn = e % BN;
            Bs[kk][nn] = B[(size_t)(k0 + kk) * NS + col0 + nn];
        }
        __syncthreads();
#pragma unroll
        for (int k = 0; k < BK; k++) {
            float a[TM], b[TN];
#pragma unroll
            for (int i = 0; i < TM; i++) a[i] = As[k][ty * TM + i];
#pragma unroll
            for (int j = 0; j < TN; j++) b[j] = Bs[k][tx * TN + j];
#pragma unroll
            for (int i = 0; i < TM; i++)
#pragma unroll
                for (int j = 0; j < TN; j++) acc[i][j] += a[i] * b[j];
        }
        __syncthreads();
    }
#pragma unroll
    for (int i = 0; i < TM; i++) {
        int gm = row0 + ty * TM + i;
        if (gm >= M) continue;
        float bv = bias ? bias[gm] : 0.f;
#pragma unroll
        for (int j = 0; j < TN; j++)
            C[(size_t)gm * NS + col0 + tx * TN + j] = acc[i][j] + bv;
    }
    (void)NN;
}

// ---------------------------------------------------------------------------
// BatchNorm statistics: one block per channel, rows of [C][NS].
// ---------------------------------------------------------------------------
__global__ void bn_stats(const float* __restrict__ x, float* __restrict__ mean,
                         float* __restrict__ istd) {
    int c = blockIdx.x;
    const float* row = x + (size_t)c * NS;
    float s = 0.f, s2 = 0.f;
    for (int i = threadIdx.x; i < NS; i += blockDim.x) {
        float v = row[i];
        s += v;
        s2 += v * v;
    }
    __shared__ float sh[256], sh2[256];
    sh[threadIdx.x] = s;
    sh2[threadIdx.x] = s2;
    __syncthreads();
    for (int st = 128; st > 0; st >>= 1) {
        if (threadIdx.x < st) {
            sh[threadIdx.x]  += sh[threadIdx.x + st];
            sh2[threadIdx.x] += sh2[threadIdx.x + st];
        }
        __syncthreads();
    }
    if (threadIdx.x == 0) {
        float m = sh[0] / (float)NS;
        float var = sh2[0] / (float)NS - m * m;
        mean[c] = m;
        istd[c] = rsqrtf(var + 1e-5f);
    }
}

// In-place BN apply (+ optional relu) on [128][NS]
__global__ void bn_apply(float* __restrict__ x, const float* __restrict__ gam,
                         const float* __restrict__ bet,
                         const float* __restrict__ mean,
                         const float* __restrict__ istd, int do_relu) {
    int i = blockIdx.x * blockDim.x + threadIdx.x;
    if (i >= 128 * NS) return;
    int c = i / NS;
    float v = (x[i] - mean[c]) * istd[c] * gam[c] + bet[c];
    if (do_relu) v = fmaxf(v, 0.f);
    x[i] = v;
}

// BN2 + residual-concat add + relu, write NCDHW output
__global__ void final_kernel(const float* __restrict__ raw,
                             const float* __restrict__ gam,
                             const float* __restrict__ bet,
                             const float* __restrict__ mean,
                             const float* __restrict__ istd,
                             const float* __restrict__ res,
                             float* __restrict__ out) {
    int i = blockIdx.x * blockDim.x + threadIdx.x;
    if (i >= 128 * NS) return;
    // output NCDHW index decomposition
    int n  = i / (128 * S_OUT);
    int co = (i / S_OUT) % 128;
    int s  = i % S_OUT;
    float v = (raw[(size_t)co * NS + n * S_OUT + s] - mean[co]) * istd[co] * gam[co] + bet[co];
    v += res[(size_t)(co & 63) * NS + n * S_OUT + s];
    out[i] = fmaxf(v, 0.f);
}

// ---------------------------------------------------------------------------
// Host launcher
// ---------------------------------------------------------------------------
extern "C" void kernel_launch(void* const* d_in, const int* in_sizes, int n_in,
                              void* d_out, int out_size) {
    (void)in_sizes; (void)n_in; (void)out_size;
    const float* x       = (const float*)d_in[0];
    const float* off1_w  = (const float*)d_in[1];
    const float* off1_b  = (const float*)d_in[2];
    const float* conv1_w = (const float*)d_in[3];
    const float* bn1_g   = (const float*)d_in[4];
    const float* bn1_b   = (const float*)d_in[5];
    const float* off2_w  = (const float*)d_in[6];
    const float* off2_b  = (const float*)d_in[7];
    const float* conv2_w = (const float*)d_in[8];
    const float* bn2_g   = (const float*)d_in[9];
    const float* bn2_b   = (const float*)d_in[10];
    float* out = (float*)d_out;

    float *cols, *off1, *off2, *out1, *out2, *res, *mean, *istd;
    cudaGetSymbolAddress((void**)&cols, g_cols);
    cudaGetSymbolAddress((void**)&off1, g_off1);
    cudaGetSymbolAddress((void**)&off2, g_off2);
    cudaGetSymbolAddress((void**)&out1, g_out1);
    cudaGetSymbolAddress((void**)&out2, g_out2);
    cudaGetSymbolAddress((void**)&res,  g_res);
    cudaGetSymbolAddress((void**)&mean, g_mean);
    cudaGetSymbolAddress((void**)&istd, g_istd);

    const int T = 256;
    long long tot;

    // residual = maxpool3d(x)
    maxpool_kernel<<<(64 * NS + T - 1) / T, T>>>(x, res);

    // off1 = conv3d(x, off1_w, off1_b, stride=2)
    tot = (long long)64 * 27 * NS;
    im2col_kernel<<<(unsigned)((tot + T - 1) / T), T>>>(x, cols, 64, 16, 56, 56, 2, 1);
    sgemm<128, 128, 8, 8, 8><<<dim3(NS / 128, (648 + 127) / 128), 256>>>(
        off1_w, cols, off1_b, off1, 648, NS, 1728);

    // out1 = deform_conv3d(x, off1, conv1_w, stride=2)
    tot = (long long)8 * 27 * NS;
    deform_im2col_kernel<<<(unsigned)((tot + T - 1) / T), T>>>(
        x, off1, cols, 64, 8, 16, 56, 56, 2, 1);
    sgemm<64, 64, 16, 4, 4><<<dim3(NS / 64, 2), 256>>>(
        conv1_w, cols, nullptr, out1, 128, NS, 1728);

    // out1 = relu(bn1(out1))
    bn_stats<<<128, 256>>>(out1, mean, istd);
    bn_apply<<<(128 * NS + T - 1) / T, T>>>(out1, bn1_g, bn1_b, mean, istd, 1);

    // off2 = conv3d(out1, off2_w, off2_b, stride=1)
    tot = (long long)128 * 27 * NS;
    im2col_kernel<<<(unsigned)((tot + T - 1) / T), T>>>(out1, cols, 128, 8, 28, 28, 1, 0);
    sgemm<128, 128, 8, 8, 8><<<dim3(NS / 128, (1296 + 127) / 128), 256>>>(
        off2_w, cols, off2_b, off2, 1296, NS, 3456);

    // out2 = deform_conv3d(out1, off2, conv2_w, stride=1)
    tot = (long long)16 * 27 * NS;
    deform_im2col_kernel<<<(unsigned)((tot + T - 1) / T), T>>>(
        out1, off2, cols, 128, 16, 8, 28, 28, 1, 0);
    sgemm<64, 64, 16, 4, 4><<<dim3(NS / 64, 2), 256>>>(
        conv2_w, cols, nullptr, out2, 128, NS, 3456);

    // out = relu(bn2(out2) + concat(residual, residual))
    bn_stats<<<128, 256>>>(out2, mean, istd);
    final_kernel<<<(128 * NS + T - 1) / T, T>>>(out2, bn2_g, bn2_b, mean, istd, res, out);
}

// round 2
// speedup vs baseline: 4.3809x; 4.3809x over previous
#include <cuda_runtime.h>
#include <math.h>
#include <stdint.h>

// ---------------------------------------------------------------------------
// Problem constants
// ---------------------------------------------------------------------------
#define NBATCH 2
#define OD 8
#define OH 28
#define OW 28
#define S_OUT 6272              // 8*28*28
#define NS 12544                // NBATCH * S_OUT

__device__ float g_cols[43352064];   // max 3456 * NS
__device__ float g_off1[8128512];    // 648  * NS
__device__ float g_off2[16257024];   // 1296 * NS
__device__ float g_out1[1605632];    // 128  * NS
__device__ float g_out2[1605632];    // 128  * NS
__device__ float g_res[802816];      // 64   * NS
__device__ float g_mean[128];
__device__ float g_istd[128];

// ---------------------------------------------------------------------------
// maxpool3d k3 s2 p1 on x -> residual [64][NS]
// ---------------------------------------------------------------------------
__global__ void maxpool_kernel(const float* __restrict__ x, float* __restrict__ res) {
    int i = blockIdx.x * blockDim.x + threadIdx.x;
    if (i >= 64 * NS) return;
    int ns = i % NS;
    int c  = i / NS;
    int n  = ns / S_OUT;
    int s  = ns % S_OUT;
    int od = s / (OH * OW);
    int oh = (s / OW) % OH;
    int ow = s % OW;
    const float* xp = x + ((size_t)(n * 64 + c)) * 16 * 56 * 56;
    int d0 = od * 2 - 1, h0 = oh * 2 - 1, w0 = ow * 2 - 1;
    int dlo = d0 < 0 ? 0 : d0, dhi = d0 + 2 > 15 ? 15 : d0 + 2;
    int hlo = h0 < 0 ? 0 : h0, hhi = h0 + 2 > 55 ? 55 : h0 + 2;
    int wlo = w0 < 0 ? 0 : w0, whi = w0 + 2 > 55 ? 55 : w0 + 2;
    float m = -INFINITY;
    for (int dd = dlo; dd <= dhi; dd++)
        for (int hh = hlo; hh <= hhi; hh++)
            for (int ww = wlo; ww <= whi; ww++)
                m = fmaxf(m, xp[(dd * 56 + hh) * 56 + ww]);
    res[(size_t)c * NS + ns] = m;
}

// ---------------------------------------------------------------------------
// Regular im2col (3x3x3, pad 1).
// ---------------------------------------------------------------------------
__global__ void im2col_kernel(const float* __restrict__ in, float* __restrict__ cols,
                              int C, int Din, int Hin, int Win, int stride, int ncdhw) {
    long long i = (long long)blockIdx.x * blockDim.x + threadIdx.x;
    long long total = (long long)C * 27 * NS;
    if (i >= total) return;
    int ns  = (int)(i % NS);
    int ct  = (int)(i / NS);
    int tap = ct % 27;
    int c   = ct / 27;
    int n   = ns / S_OUT;
    int s   = ns % S_OUT;
    int od = s / (OH * OW);
    int oh = (s / OW) % OH;
    int ow = s % OW;
    int kd = tap / 9, kh = (tap / 3) % 3, kw = tap % 3;
    int id = od * stride - 1 + kd;
    int ih = oh * stride - 1 + kh;
    int iw = ow * stride - 1 + kw;
    float v = 0.f;
    if (id >= 0 && id < Din && ih >= 0 && ih < Hin && iw >= 0 && iw < Win) {
        size_t Sin = (size_t)Din * Hin * Win;
        size_t base = ncdhw ? ((size_t)(n * C + c)) * Sin
                            : ((size_t)c * NBATCH + n) * Sin;
        v = in[base + ((size_t)id * Hin + ih) * Win + iw];
    }
    cols[(size_t)ct * NS + ns] = v;
}

// ---------------------------------------------------------------------------
// Deformable im2col (one thread per (group, tap, ns); reuses corner
// weights/indices across the 8 channels of the group).
// ---------------------------------------------------------------------------
__global__ void deform_im2col_kernel(const float* __restrict__ in,
                                     const float* __restrict__ off,
                                     float* __restrict__ cols,
                                     int C, int G, int Din, int Hin, int Win,
                                     int stride, int ncdhw) {
    long long i = (long long)blockIdx.x * blockDim.x + threadIdx.x;
    long long total = (long long)G * 27 * NS;
    if (i >= total) return;
    int ns  = (int)(i % NS);
    int gt  = (int)(i / NS);
    int tap = gt % 27;
    int g   = gt / 27;
    int n   = ns / S_OUT;
    int s   = ns % S_OUT;
    int od = s / (OH * OW);
    int oh = (s / OW) % OH;
    int ow = s % OW;
    int kd = tap / 9, kh = (tap / 3) % 3, kw = tap % 3;

    size_t ob = ((size_t)(g * 3) * 27 + tap) * NS + ns;
    float pd = off[ob]                     + (float)(od * stride - 1 + kd);
    float ph = off[ob + (size_t)27 * NS]   + (float)(oh * stride - 1 + kh);
    float pw = off[ob + (size_t)54 * NS]   + (float)(ow * stride - 1 + kw);

    float d0f = floorf(pd), h0f = floorf(ph), w0f = floorf(pw);
    int d0 = (int)d0f, h0 = (int)h0f, w0 = (int)w0f;
    float fd = pd - d0f, fh = ph - h0f, fw = pw - w0f;

    float wt8[8];
    int   idx8[8];
    int Sin = Din * Hin * Win;
#pragma unroll
    for (int cr = 0; cr < 8; cr++) {
        int cd = cr >> 2, ch = (cr >> 1) & 1, cw = cr & 1;
        int di = d0 + cd, hi = h0 + ch, wi = w0 + cw;
        bool valid = (di >= 0) && (di < Din) && (hi >= 0) && (hi < Hin) &&
                     (wi >= 0) && (wi < Win);
        float wt = (cd ? fd : 1.f - fd) * (ch ? fh : 1.f - fh) * (cw ? fw : 1.f - fw);
        wt8[cr] = valid ? wt : 0.f;
        int dic = di < 0 ? 0 : (di > Din - 1 ? Din - 1 : di);
        int hic = hi < 0 ? 0 : (hi > Hin - 1 ? Hin - 1 : hi);
        int wic = wi < 0 ? 0 : (wi > Win - 1 ? Win - 1 : wi);
        idx8[cr] = (dic * Hin + hic) * Win + wic;
    }
#pragma unroll
    for (int cc = 0; cc < 8; cc++) {
        int c = g * 8 + cc;
        size_t base = ncdhw ? ((size_t)(n * C + c)) * Sin
                            : ((size_t)c * NBATCH + n) * Sin;
        const float* bp = in + base;
        float acc = 0.f;
#pragma unroll
        for (int cr = 0; cr < 8; cr++) acc += wt8[cr] * bp[idx8[cr]];
        cols[((size_t)c * 27 + tap) * NS + ns] = acc;
    }
}

// ---------------------------------------------------------------------------
// TF32 tensor-core GEMM: C[M][NS] = A[M][K] * B[K][NS] (+bias).
// 128x128 block tile, BK=16, cp.async double buffer, 8 warps (2x4),
// mma.sync.m16n8k8.tf32. K % 16 == 0, NS % 128 == 0 guaranteed.
// ---------------------------------------------------------------------------
#define GBM 128
#define GBN 128
#define GBK 16
#define AP  20    // As row length in words (BK + 4): conflict-free frag loads
#define BP  136   // Bs row length in words (BN + 8)

__device__ __forceinline__ void cpasync16(float* dst, const float* src, bool pred) {
    uint32_t d = (uint32_t)__cvta_generic_to_shared(dst);
    int sz = pred ? 16 : 0;
    asm volatile("cp.async.cg.shared.global [%0], [%1], 16, %2;\n"
                 :: "r"(d), "l"(src), "r"(sz));
}

__device__ __forceinline__ void mma_tf32(float* c, float a0, float a1, float a2,
                                         float a3, float b0, float b1) {
    asm volatile(
        "mma.sync.aligned.m16n8k8.row.col.f32.tf32.tf32.f32 "
        "{%0,%1,%2,%3}, {%4,%5,%6,%7}, {%8,%9}, {%0,%1,%2,%3};\n"
        : "+f"(c[0]), "+f"(c[1]), "+f"(c[2]), "+f"(c[3])
        : "r"(__float_as_uint(a0)), "r"(__float_as_uint(a1)),
          "r"(__float_as_uint(a2)), "r"(__float_as_uint(a3)),
          "r"(__float_as_uint(b0)), "r"(__float_as_uint(b1)));
}

__global__ __launch_bounds__(256, 2) void gemm_tf32(
    const float* __restrict__ A, const float* __restrict__ B,
    const float* __restrict__ bias, float* __restrict__ C, int M, int K) {
    __shared__ float As[2][GBM * AP];
    __shared__ float Bs[2][GBK * BP];

    int tid  = threadIdx.x;
    int warp = tid >> 5, lane = tid & 31;
    int wm = warp >> 2, wn = warp & 3;      // warps: 2 along M, 4 along N
    int rg = lane >> 2, cg = lane & 3;      // mma groupID / threadID-in-group
    int row0 = blockIdx.x * GBM;
    int col0 = blockIdx.y * GBN;

    // cp.async slot assignment
    int a_m  = tid >> 1;                    // 0..127
    int a_k0 = (tid & 1) * 8;               // two float4 at k0, k0+4
    int b_k  = tid >> 4;                    // 0..15
    int b_n0 = (tid & 15) * 8;              // two float4 at n0, n0+4

    int gmA = row0 + a_m;
    bool aval = gmA < M;
    const float* a_src = A + (size_t)(aval ? gmA : (M - 1)) * K + a_k0;
    const float* b_src = B + (size_t)b_k * NS + col0 + b_n0;

    float acc[4][4][4];
#pragma unroll
    for (int i = 0; i < 4; i++)
#pragma unroll
        for (int j = 0; j < 4; j++)
#pragma unroll
            for (int r = 0; r < 4; r++) acc[i][j][r] = 0.f;

    int T = K / GBK;

    // prologue: tile 0 -> buf 0
    {
        float* ad = &As[0][a_m * AP + a_k0];
        cpasync16(ad, a_src, aval);
        cpasync16(ad + 4, a_src + 4, aval);
        float* bd = &Bs[0][b_k * BP + b_n0];
        cpasync16(bd, b_src, true);
        cpasync16(bd + 4, b_src + 4, true);
        asm volatile("cp.async.commit_group;\n");
    }

    for (int it = 0; it < T; it++) {
        int buf = it & 1;
        if (it + 1 < T) {
            int k0 = (it + 1) * GBK;
            float* ad = &As[buf ^ 1][a_m * AP + a_k0];
            cpasync16(ad, a_src + k0, aval);
            cpasync16(ad + 4, a_src + k0 + 4, aval);
            float* bd = &Bs[buf ^ 1][b_k * BP + b_n0];
            const float* bs = b_src + (size_t)k0 * NS;
            cpasync16(bd, bs, true);
            cpasync16(bd + 4, bs + 4, true);
            asm volatile("cp.async.commit_group;\n");
            asm volatile("cp.async.wait_group 1;\n");
        } else {
            asm volatile("cp.async.wait_group 0;\n");
        }
        __syncthreads();

#pragma unroll
        for (int ks = 0; ks < 2; ks++) {
            int kb = ks * 8;
            float af[4][4];
#pragma unroll
            for (int i = 0; i < 4; i++) {
                int mb = wm * 64 + i * 16;
                af[i][0] = As[buf][(mb + rg) * AP + kb + cg];
                af[i][1] = As[buf][(mb + 8 + rg) * AP + kb + cg];
                af[i][2] = As[buf][(mb + rg) * AP + kb + cg + 4];
                af[i][3] = As[buf][(mb + 8 + rg) * AP + kb + cg + 4];
            }
            float bf[4][2];
#pragma unroll
            for (int j = 0; j < 4; j++) {
                int nb = wn * 32 + j * 8 + rg;
                bf[j][0] = Bs[buf][(kb + cg) * BP + nb];
                bf[j][1] = Bs[buf][(kb + cg + 4) * BP + nb];
            }
#pragma unroll
            for (int i = 0; i < 4; i++)
#pragma unroll
                for (int j = 0; j < 4; j++)
                    mma_tf32(acc[i][j], af[i][0], af[i][1], af[i][2], af[i][3],
                             bf[j][0], bf[j][1]);
        }
        __syncthreads();
    }

    // epilogue
#pragma unroll
    for (int i = 0; i < 4; i++) {
        int gm0 = row0 + wm * 64 + i * 16 + rg;
        int gm1 = gm0 + 8;
#pragma unroll
        for (int j = 0; j < 4; j++) {
            int gc = col0 + wn * 32 + j * 8 + 2 * cg;
            if (gm0 < M) {
                float bv = bias ? bias[gm0] : 0.f;
                float2 v = make_float2(acc[i][j][0] + bv, acc[i][j][1] + bv);
                *(float2*)&C[(size_t)gm0 * NS + gc] = v;
            }
            if (gm1 < M) {
                float bv = bias ? bias[gm1] : 0.f;
                float2 v = make_float2(acc[i][j][2] + bv, acc[i][j][3] + bv);
                *(float2*)&C[(size_t)gm1 * NS + gc] = v;
            }
        }
    }
}

// ---------------------------------------------------------------------------
// BatchNorm statistics: one block per channel, rows of [C][NS].
// ---------------------------------------------------------------------------
__global__ void bn_stats(const float* __restrict__ x, float* __restrict__ mean,
                         float* __restrict__ istd) {
    int c = blockIdx.x;
    const float* row = x + (size_t)c * NS;
    float s = 0.f, s2 = 0.f;
    for (int i = threadIdx.x; i < NS; i += blockDim.x) {
        float v = row[i];
        s += v;
        s2 += v * v;
    }
    __shared__ float sh[256], sh2[256];
    sh[threadIdx.x] = s;
    sh2[threadIdx.x] = s2;
    __syncthreads();
    for (int st = 128; st > 0; st >>= 1) {
        if (threadIdx.x < st) {
            sh[threadIdx.x]  += sh[threadIdx.x + st];
            sh2[threadIdx.x] += sh2[threadIdx.x + st];
        }
        __syncthreads();
    }
    if (threadIdx.x == 0) {
        float m = sh[0] / (float)NS;
        float var = sh2[0] / (float)NS - m * m;
        mean[c] = m;
        istd[c] = rsqrtf(var + 1e-5f);
    }
}

__global__ void bn_apply(float* __restrict__ x, const float* __restrict__ gam,
                         const float* __restrict__ bet,
                         const float* __restrict__ mean,
                         const float* __restrict__ istd, int do_relu) {
    int i = blockIdx.x * blockDim.x + threadIdx.x;
    if (i >= 128 * NS) return;
    int c = i / NS;
    float v = (x[i] - mean[c]) * istd[c] * gam[c] + bet[c];
    if (do_relu) v = fmaxf(v, 0.f);
    x[i] = v;
}

__global__ void final_kernel(const float* __restrict__ raw,
                             const float* __restrict__ gam,
                             const float* __restrict__ bet,
                             const float* __restrict__ mean,
                             const float* __restrict__ istd,
                             const float* __restrict__ res,
                             float* __restrict__ out) {
    int i = blockIdx.x * blockDim.x + threadIdx.x;
    if (i >= 128 * NS) return;
    int n  = i / (128 * S_OUT);
    int co = (i / S_OUT) % 128;
    int s  = i % S_OUT;
    float v = (raw[(size_t)co * NS + n * S_OUT + s] - mean[co]) * istd[co] * gam[co] + bet[co];
    v += res[(size_t)(co & 63) * NS + n * S_OUT + s];
    out[i] = fmaxf(v, 0.f);
}

// ---------------------------------------------------------------------------
// Host launcher
// ---------------------------------------------------------------------------
extern "C" void kernel_launch(void* const* d_in, const int* in_sizes, int n_in,
                              void* d_out, int out_size) {
    (void)in_sizes; (void)n_in; (void)out_size;
    const float* x       = (const float*)d_in[0];
    const float* off1_w  = (const float*)d_in[1];
    const float* off1_b  = (const float*)d_in[2];
    const float* conv1_w = (const float*)d_in[3];
    const float* bn1_g   = (const float*)d_in[4];
    const float* bn1_b   = (const float*)d_in[5];
    const float* off2_w  = (const float*)d_in[6];
    const float* off2_b  = (const float*)d_in[7];
    const float* conv2_w = (const float*)d_in[8];
    const float* bn2_g   = (const float*)d_in[9];
    const float* bn2_b   = (const float*)d_in[10];
    float* out = (float*)d_out;

    float *cols, *off1, *off2, *out1, *out2, *res, *mean, *istd;
    cudaGetSymbolAddress((void**)&cols, g_cols);
    cudaGetSymbolAddress((void**)&off1, g_off1);
    cudaGetSymbolAddress((void**)&off2, g_off2);
    cudaGetSymbolAddress((void**)&out1, g_out1);
    cudaGetSymbolAddress((void**)&out2, g_out2);
    cudaGetSymbolAddress((void**)&res,  g_res);
    cudaGetSymbolAddress((void**)&mean, g_mean);
    cudaGetSymbolAddress((void**)&istd, g_istd);

    const int T = 256;
    long long tot;
    const int NT = NS / GBN;   // 98 column tiles

    // residual = maxpool3d(x)
    maxpool_kernel<<<(64 * NS + T - 1) / T, T>>>(x, res);

    // off1 = conv3d(x, off1_w, off1_b, stride=2)
    tot = (long long)64 * 27 * NS;
    im2col_kernel<<<(unsigned)((tot + T - 1) / T), T>>>(x, cols, 64, 16, 56, 56, 2, 1);
    gemm_tf32<<<dim3((648 + GBM - 1) / GBM, NT), 256>>>(off1_w, cols, off1_b, off1, 648, 1728);

    // out1 = deform_conv3d(x, off1, conv1_w, stride=2)
    tot = (long long)8 * 27 * NS;
    deform_im2col_kernel<<<(unsigned)((tot + T - 1) / T), T>>>(
        x, off1, cols, 64, 8, 16, 56, 56, 2, 1);
    gemm_tf32<<<dim3(1, NT), 256>>>(conv1_w, cols, nullptr, out1, 128, 1728);

    // out1 = relu(bn1(out1))
    bn_stats<<<128, 256>>>(out1, mean, istd);
    bn_apply<<<(128 * NS + T - 1) / T, T>>>(out1, bn1_g, bn1_b, mean, istd, 1);

    // off2 = conv3d(out1, off2_w, off2_b, stride=1)
    tot = (long long)128 * 27 * NS;
    im2col_kernel<<<(unsigned)((tot + T - 1) / T), T>>>(out1, cols, 128, 8, 28, 28, 1, 0);
    gemm_tf32<<<dim3((1296 + GBM - 1) / GBM, NT), 256>>>(off2_w, cols, off2_b, off2, 1296, 3456);

    // out2 = deform_conv3d(out1, off2, conv2_w, stride=1)
    tot = (long long)16 * 27 * NS;
    deform_im2col_kernel<<<(unsigned)((tot + T - 1) / T), T>>>(
        out1, off2, cols, 128, 16, 8, 28, 28, 1, 0);
    gemm_tf32<<<dim3(1, NT), 256>>>(conv2_w, cols, nullptr, out2, 128, 3456);

    // out = relu(bn2(out2) + concat(residual, residual))
    bn_stats<<<128, 256>>>(out2, mean, istd);
    final_kernel<<<(128 * NS + T - 1) / T, T>>>(out2, bn2_g, bn2_b, mean, istd, res, out);
}